// round 2
// baseline (speedup 1.0000x reference)
#include <cuda_runtime.h>
#include <cuda_bf16.h>
#include <stdint.h>

// ============================================================================
// Problem constants
// ============================================================================
#define N_TOT 8192        // bsz * n_views
#define BSZ   4096
#define DIM   128
#define INV_T 14.285714285714286f   // 1 / 0.07
#define SPAD  136                    // padded SMEM row stride (elements)

// ============================================================================
// Device globals (no dynamic allocation permitted)
// ============================================================================
__device__ __nv_bfloat16 g_F[(size_t)N_TOT * DIM];     // normalized feats, view-major
__device__ float g_pA[(size_t)128 * N_TOT];            // per-(colTile,half) partials
__device__ float g_pW[(size_t)128 * N_TOT];
__device__ float g_pD[(size_t)128 * N_TOT];
__device__ float g_loss[N_TOT];

__device__ __forceinline__ uint32_t smem_u32(const void* smem_ptr) {
    uint32_t addr;
    asm("{ .reg .u64 tmp; cvta.to.shared.u64 tmp, %1; cvt.u32.u64 %0, tmp; }"
        : "=r"(addr) : "l"(smem_ptr));
    return addr;
}

// ============================================================================
// Kernel 1: normalize features (fp32) -> bf16, view-major [8192, 128]
// ============================================================================
__global__ void k_norm(const float* __restrict__ feats) {
    int row  = blockIdx.x * 8 + (threadIdx.x >> 5);   // 8 warps/CTA, 1024 CTAs
    int lane = threadIdx.x & 31;
    int b = row & (BSZ - 1);
    int v = row >> 12;
    const float4* src = reinterpret_cast<const float4*>(feats)
                        + (size_t)(b * 2 + v) * (DIM / 4) + lane;
    float4 x = *src;
    float ss = fmaf(x.x, x.x, fmaf(x.y, x.y, fmaf(x.z, x.z, x.w * x.w)));
#pragma unroll
    for (int o = 16; o; o >>= 1) ss += __shfl_xor_sync(0xffffffffu, ss, o);
    float inv = rsqrtf(ss + 1e-12f);
    __nv_bfloat162 lo = __floats2bfloat162_rn(x.x * inv, x.y * inv);
    __nv_bfloat162 hi = __floats2bfloat162_rn(x.z * inv, x.w * inv);
    uint2 pk;
    pk.x = *reinterpret_cast<uint32_t*>(&lo);
    pk.y = *reinterpret_cast<uint32_t*>(&hi);
    reinterpret_cast<uint2*>(g_F)[(size_t)row * (DIM / 4) + lane] = pk;
}

// ============================================================================
// Kernel 2: fused 128x128 tile kernel via mma.sync bf16 (base ISA, no tcgen05)
//   C-tile = F[tI] @ F[tJ]^T ; epilogue computes per-row partials:
//   A=sum(w*cos), W=sum(w), D=sum_{k!=i} exp((cos-1)/T)
// ============================================================================
// dynamic SMEM layout:
//   sA: [0, 34816)      128 rows x SPAD bf16
//   sB: [34816, 69632)
//   s_clab: [69632, 70144)
#define SMEM_BYTES (2 * 128 * SPAD * 2 + 512)

__device__ __forceinline__ void ldmatrix_x4(uint32_t* a, uint32_t addr) {
    asm volatile("ldmatrix.sync.aligned.m8n8.x4.shared.b16 {%0,%1,%2,%3}, [%4];"
                 : "=r"(a[0]), "=r"(a[1]), "=r"(a[2]), "=r"(a[3]) : "r"(addr));
}

__device__ __forceinline__ void mma_bf16(float* c, const uint32_t* a,
                                         uint32_t b0, uint32_t b1) {
    asm volatile(
        "mma.sync.aligned.m16n8k16.row.col.f32.bf16.bf16.f32 "
        "{%0,%1,%2,%3}, {%4,%5,%6,%7}, {%8,%9}, {%0,%1,%2,%3};"
        : "+f"(c[0]), "+f"(c[1]), "+f"(c[2]), "+f"(c[3])
        : "r"(a[0]), "r"(a[1]), "r"(a[2]), "r"(a[3]), "r"(b0), "r"(b1));
}

__global__ void __launch_bounds__(256)
k_main(const float* __restrict__ labels) {
    extern __shared__ char smem[];
    __nv_bfloat16* sA = reinterpret_cast<__nv_bfloat16*>(smem);
    __nv_bfloat16* sB = reinterpret_cast<__nv_bfloat16*>(smem + 128 * SPAD * 2);
    float* s_clab = reinterpret_cast<float*>(smem + 2 * 128 * SPAD * 2);

    int tid  = threadIdx.x;
    int wid  = tid >> 5;
    int lane = tid & 31;
    int tJ = blockIdx.x;   // column tile
    int tI = blockIdx.y;   // row tile

    if (tid < 128) s_clab[tid] = __ldg(&labels[(tJ * 128 + tid) & (BSZ - 1)]);

    // Stage A and B tiles into padded SMEM (coalesced 16B chunks)
    {
        const uint4* srcA = reinterpret_cast<const uint4*>(g_F + (size_t)tI * 128 * DIM);
        const uint4* srcB = reinterpret_cast<const uint4*>(g_F + (size_t)tJ * 128 * DIM);
#pragma unroll
        for (int it = 0; it < 8; ++it) {
            int c   = it * 256 + tid;
            int row = c >> 4;
            int ci  = c & 15;
            reinterpret_cast<uint4*>(sA + row * SPAD)[ci] = srcA[row * 16 + ci];
            reinterpret_cast<uint4*>(sB + row * SPAD)[ci] = srcB[row * 16 + ci];
        }
    }
    __syncthreads();

    int rg = wid & 3;        // row group: rows rg*32 .. +32
    int cg = wid >> 2;       // col group: cols cg*64 .. +64

    float acc[2][8][4];
#pragma unroll
    for (int mt = 0; mt < 2; ++mt)
#pragma unroll
        for (int nt = 0; nt < 8; ++nt)
#pragma unroll
            for (int e = 0; e < 4; ++e) acc[mt][nt][e] = 0.f;

    uint32_t sA_b = smem_u32(sA);
    uint32_t sB_b = smem_u32(sB);
    // ldmatrix A addr: row = rg*32 + mt*16 + (lane&15), elem col = (lane>>4)*8 + kc*16
    uint32_t a_addr0 = sA_b + (uint32_t)(((rg * 32 + (lane & 15)) * SPAD
                                          + ((lane >> 4) << 3)) * 2);
    // B direct-load addr: j = cg*64 + nt*8 + lane/4 ; k0 = kc*16 + (lane&3)*2
    uint32_t b_addr0 = sB_b + (uint32_t)(((cg * 64 + (lane >> 2)) * SPAD
                                          + ((lane & 3) << 1)) * 2);

#pragma unroll
    for (int kc = 0; kc < 8; ++kc) {
        uint32_t a[2][4];
#pragma unroll
        for (int mt = 0; mt < 2; ++mt)
            ldmatrix_x4(a[mt], a_addr0 + (uint32_t)(mt * 16 * SPAD * 2 + kc * 32));
#pragma unroll
        for (int nt = 0; nt < 8; ++nt) {
            uint32_t baddr = b_addr0 + (uint32_t)(nt * 8 * SPAD * 2 + kc * 32);
            uint32_t b0, b1;
            asm volatile("ld.shared.b32 %0, [%1];" : "=r"(b0) : "r"(baddr));
            asm volatile("ld.shared.b32 %0, [%1];" : "=r"(b1) : "r"(baddr + 16));
            mma_bf16(acc[0][nt], a[0], b0, b1);
            mma_bf16(acc[1][nt], a[1], b0, b1);
        }
    }

    // ---------------- Epilogue ----------------
    // acc[mt][nt][e]: row_local = rg*32 + mt*16 + (e>>1)*8 + lane/4
    //                 col_local = cg*64 + nt*8 + (lane&3)*2 + (e&1)
    int rl = rg * 32 + (lane >> 2);
    float labi[4];
#pragma unroll
    for (int q = 0; q < 4; ++q)
        labi[q] = __ldg(&labels[(tI * 128 + rl + q * 8) & (BSZ - 1)]);

    bool dtile = (tI == tJ);
    float sAr[4] = {0.f, 0.f, 0.f, 0.f};
    float sWr[4] = {0.f, 0.f, 0.f, 0.f};
    float sDr[4] = {0.f, 0.f, 0.f, 0.f};

#pragma unroll
    for (int nt = 0; nt < 8; ++nt) {
        int clbase = cg * 64 + nt * 8 + ((lane & 3) << 1);
        float lj0 = s_clab[clbase];
        float lj1 = s_clab[clbase + 1];
#pragma unroll
        for (int mt = 0; mt < 2; ++mt) {
#pragma unroll
            for (int e = 0; e < 4; ++e) {
                int q  = mt * 2 + (e >> 1);
                int rr = rl + q * 8;                   // local row
                int cc = clbase + (e & 1);             // local col
                float cosv = acc[mt][nt][e];
                float dy = labi[q] - ((e & 1) ? lj1 : lj0);
                float w  = __expf(dy * dy * -0.5f);
                bool dg  = dtile && (rr == cc);
                float ev = dg ? 0.f : __expf((cosv - 1.0f) * INV_T);
                if (dg) cosv = 1.0f;
                sAr[q] = fmaf(w, cosv, sAr[q]);
                sWr[q] += w;
                sDr[q] += ev;
            }
        }
    }

    // Reduce across the 4 lanes that share each row (lane%4 = 0..3)
#pragma unroll
    for (int q = 0; q < 4; ++q) {
        sAr[q] += __shfl_xor_sync(0xffffffffu, sAr[q], 1);
        sAr[q] += __shfl_xor_sync(0xffffffffu, sAr[q], 2);
        sWr[q] += __shfl_xor_sync(0xffffffffu, sWr[q], 1);
        sWr[q] += __shfl_xor_sync(0xffffffffu, sWr[q], 2);
        sDr[q] += __shfl_xor_sync(0xffffffffu, sDr[q], 1);
        sDr[q] += __shfl_xor_sync(0xffffffffu, sDr[q], 2);
    }

    if ((lane & 3) == 0) {
        int slot = tJ * 2 + cg;
#pragma unroll
        for (int q = 0; q < 4; ++q) {
            int gi = tI * 128 + rl + q * 8;
            g_pA[(size_t)slot * N_TOT + gi] = sAr[q];
            g_pW[(size_t)slot * N_TOT + gi] = sWr[q];
            g_pD[(size_t)slot * N_TOT + gi] = sDr[q];
        }
    }
}

// ============================================================================
// Kernel 3: per-row reduction of 128 partial slots -> per-row loss
// ============================================================================
__global__ void k_final1() {
    int row = blockIdx.x * 256 + threadIdx.x;   // 32 CTAs x 256 = 8192
    float A = 0.f, W = 0.f, D = 0.f;
#pragma unroll 4
    for (int s = 0; s < 128; ++s) {
        A += g_pA[(size_t)s * N_TOT + row];
        W += g_pW[(size_t)s * N_TOT + row];
        D += g_pD[(size_t)s * N_TOT + row];
    }
    float mlpp = (A - W) * INV_T / W - logf(D + 1e-8f);
    g_loss[row] = -mlpp;
}

// ============================================================================
// Kernel 4: mean over rows -> scalar
// ============================================================================
__global__ void k_final2(float* __restrict__ out) {
    __shared__ float red[32];
    int tid = threadIdx.x;  // 1024
    float s = 0.f;
    for (int r = tid; r < N_TOT; r += 1024) s += g_loss[r];
#pragma unroll
    for (int o = 16; o; o >>= 1) s += __shfl_xor_sync(0xffffffffu, s, o);
    if ((tid & 31) == 0) red[tid >> 5] = s;
    __syncthreads();
    if (tid < 32) {
        float v = red[tid];
#pragma unroll
        for (int o = 16; o; o >>= 1) v += __shfl_xor_sync(0xffffffffu, v, o);
        if (tid == 0) out[0] = v * (1.0f / (float)N_TOT);
    }
}

// ============================================================================
// Launch
// ============================================================================
extern "C" void kernel_launch(void* const* d_in, const int* in_sizes, int n_in,
                              void* d_out, int out_size) {
    const float* feats  = (const float*)d_in[0];
    const float* labels = (const float*)d_in[1];
    if (n_in >= 2 && in_sizes[0] == BSZ && in_sizes[1] != BSZ) {
        feats  = (const float*)d_in[1];
        labels = (const float*)d_in[0];
    }

    cudaFuncSetAttribute(k_main, cudaFuncAttributeMaxDynamicSharedMemorySize,
                         SMEM_BYTES);

    k_norm<<<N_TOT / 8, 256>>>(feats);

    dim3 grid(64, 64);
    k_main<<<grid, 256, SMEM_BYTES>>>(labels);

    k_final1<<<32, 256>>>();
    k_final2<<<1, 1024>>>((float*)d_out);
}

// round 3
// speedup vs baseline: 1.4179x; 1.4179x over previous
#include <cuda_runtime.h>
#include <cuda_bf16.h>
#include <stdint.h>

// ============================================================================
// Problem constants
// ============================================================================
#define N_TOT 8192        // bsz * n_views
#define BSZ   4096
#define DIM   128
#define INV_T 14.285714285714286f   // 1 / 0.07
#define SPAD  136                    // padded SMEM row stride (elements)
#define NTILE 64
#define NPAIR 2080                   // 64*65/2 upper-triangular tiles

// ============================================================================
// Device globals (no dynamic allocation permitted)
// ============================================================================
__device__ __nv_bfloat16 g_F[(size_t)N_TOT * DIM];     // normalized feats, view-major
__device__ float g_pA[(size_t)128 * N_TOT];            // per-slot partials
__device__ float g_pW[(size_t)128 * N_TOT];
__device__ float g_pD[(size_t)128 * N_TOT];
__device__ float g_bpart[32];

__device__ __forceinline__ uint32_t smem_u32(const void* smem_ptr) {
    uint32_t addr;
    asm("{ .reg .u64 tmp; cvta.to.shared.u64 tmp, %1; cvt.u32.u64 %0, tmp; }"
        : "=r"(addr) : "l"(smem_ptr));
    return addr;
}

// ============================================================================
// Kernel 1: normalize features (fp32) -> bf16, view-major [8192, 128]
// ============================================================================
__global__ void k_norm(const float* __restrict__ feats) {
    int row  = blockIdx.x * 8 + (threadIdx.x >> 5);   // 8 warps/CTA, 1024 CTAs
    int lane = threadIdx.x & 31;
    int b = row & (BSZ - 1);
    int v = row >> 12;
    const float4* src = reinterpret_cast<const float4*>(feats)
                        + (size_t)(b * 2 + v) * (DIM / 4) + lane;
    float4 x = *src;
    float ss = fmaf(x.x, x.x, fmaf(x.y, x.y, fmaf(x.z, x.z, x.w * x.w)));
#pragma unroll
    for (int o = 16; o; o >>= 1) ss += __shfl_xor_sync(0xffffffffu, ss, o);
    float inv = rsqrtf(ss + 1e-12f);
    __nv_bfloat162 lo = __floats2bfloat162_rn(x.x * inv, x.y * inv);
    __nv_bfloat162 hi = __floats2bfloat162_rn(x.z * inv, x.w * inv);
    uint2 pk;
    pk.x = *reinterpret_cast<uint32_t*>(&lo);
    pk.y = *reinterpret_cast<uint32_t*>(&hi);
    reinterpret_cast<uint2*>(g_F)[(size_t)row * (DIM / 4) + lane] = pk;
}

// ============================================================================
// Kernel 2: fused 128x128 tile kernel via mma.sync bf16, UPPER-TRIANGULAR only.
//   C-tile = F[tI] @ F[tJ]^T (tI <= tJ). Row partials serve block tI;
//   column partials (tile transposed, valid by symmetry of cos/w/e) serve
//   block tJ. Diagonal tiles emit rows only.
// ============================================================================
// dynamic SMEM layout:
//   sA: [0, 34816)      128 rows x SPAD bf16   (overlaid by scol after MMA)
//   sB: [34816, 69632)
//   s_clab: [69632, 70144)   column labels
//   s_rlab: [70144, 70656)   row labels
#define SMEM_BYTES (2 * 128 * SPAD * 2 + 1024)

__device__ __forceinline__ void ldmatrix_x4(uint32_t* a, uint32_t addr) {
    asm volatile("ldmatrix.sync.aligned.m8n8.x4.shared.b16 {%0,%1,%2,%3}, [%4];"
                 : "=r"(a[0]), "=r"(a[1]), "=r"(a[2]), "=r"(a[3]) : "r"(addr));
}

__device__ __forceinline__ void mma_bf16(float* c, const uint32_t* a,
                                         uint32_t b0, uint32_t b1) {
    asm volatile(
        "mma.sync.aligned.m16n8k16.row.col.f32.bf16.bf16.f32 "
        "{%0,%1,%2,%3}, {%4,%5,%6,%7}, {%8,%9}, {%0,%1,%2,%3};"
        : "+f"(c[0]), "+f"(c[1]), "+f"(c[2]), "+f"(c[3])
        : "r"(a[0]), "r"(a[1]), "r"(a[2]), "r"(a[3]), "r"(b0), "r"(b1));
}

__global__ void __launch_bounds__(256)
k_main(const float* __restrict__ labels) {
    extern __shared__ char smem[];
    __nv_bfloat16* sA = reinterpret_cast<__nv_bfloat16*>(smem);
    __nv_bfloat16* sB = reinterpret_cast<__nv_bfloat16*>(smem + 128 * SPAD * 2);
    float* s_clab = reinterpret_cast<float*>(smem + 2 * 128 * SPAD * 2);
    float* s_rlab = s_clab + 128;
    float* scol   = reinterpret_cast<float*>(smem);   // overlay after MMA

    int tid  = threadIdx.x;
    int wid  = tid >> 5;
    int lane = tid & 31;

    // Map linear block id -> upper-triangular (tI, tJ), tI <= tJ
    int t = blockIdx.x;
    int tI;
    {
        float disc = (float)((2 * NTILE + 1) * (2 * NTILE + 1) - 8 * t);
        tI = (int)(((float)(2 * NTILE + 1) - sqrtf(disc)) * 0.5f);
        if (tI < 0) tI = 0;
        if (tI > NTILE - 1) tI = NTILE - 1;
        // exact fixup
        while (tI + 1 <= NTILE - 1 &&
               (tI + 1) * NTILE - ((tI + 1) * tI) / 2 <= t) ++tI;
        while (tI * NTILE - (tI * (tI - 1)) / 2 > t) --tI;
    }
    int tJ = tI + (t - (tI * NTILE - (tI * (tI - 1)) / 2));
    bool dtile = (tI == tJ);

    if (tid < 128) {
        s_clab[tid] = __ldg(&labels[(tJ * 128 + tid) & (BSZ - 1)]);
        s_rlab[tid] = __ldg(&labels[(tI * 128 + tid) & (BSZ - 1)]);
    }

    // Stage A and B tiles into padded SMEM (coalesced 16B chunks)
    {
        const uint4* srcA = reinterpret_cast<const uint4*>(g_F + (size_t)tI * 128 * DIM);
        const uint4* srcB = reinterpret_cast<const uint4*>(g_F + (size_t)tJ * 128 * DIM);
#pragma unroll
        for (int it = 0; it < 8; ++it) {
            int c   = it * 256 + tid;
            int row = c >> 4;
            int ci  = c & 15;
            reinterpret_cast<uint4*>(sA + row * SPAD)[ci] = srcA[row * 16 + ci];
            reinterpret_cast<uint4*>(sB + row * SPAD)[ci] = srcB[row * 16 + ci];
        }
    }
    __syncthreads();

    int rg = wid & 3;        // row group: rows rg*32 .. +32
    int cg = wid >> 2;       // col group: cols cg*64 .. +64

    float acc[2][8][4];
#pragma unroll
    for (int mt = 0; mt < 2; ++mt)
#pragma unroll
        for (int nt = 0; nt < 8; ++nt)
#pragma unroll
            for (int e = 0; e < 4; ++e) acc[mt][nt][e] = 0.f;

    uint32_t sA_b = smem_u32(sA);
    uint32_t sB_b = smem_u32(sB);
    uint32_t a_addr0 = sA_b + (uint32_t)(((rg * 32 + (lane & 15)) * SPAD
                                          + ((lane >> 4) << 3)) * 2);
    uint32_t b_addr0 = sB_b + (uint32_t)(((cg * 64 + (lane >> 2)) * SPAD
                                          + ((lane & 3) << 1)) * 2);

#pragma unroll
    for (int kc = 0; kc < 8; ++kc) {
        uint32_t a[2][4];
#pragma unroll
        for (int mt = 0; mt < 2; ++mt)
            ldmatrix_x4(a[mt], a_addr0 + (uint32_t)(mt * 16 * SPAD * 2 + kc * 32));
#pragma unroll
        for (int nt = 0; nt < 8; ++nt) {
            uint32_t baddr = b_addr0 + (uint32_t)(nt * 8 * SPAD * 2 + kc * 32);
            uint32_t b0, b1;
            asm volatile("ld.shared.b32 %0, [%1];" : "=r"(b0) : "r"(baddr));
            asm volatile("ld.shared.b32 %0, [%1];" : "=r"(b1) : "r"(baddr + 16));
            mma_bf16(acc[0][nt], a[0], b0, b1);
            mma_bf16(acc[1][nt], a[1], b0, b1);
        }
    }

    // SMEM tiles are dead now; scol overlays sA.
    __syncthreads();

    // ---------------- Epilogue ----------------
    // acc[mt][nt][e]: row_local = rg*32 + mt*16 + (e>>1)*8 + lane/4
    //                 col_local = cg*64 + nt*8 + (lane&3)*2 + (e&1)
    int rl = rg * 32 + (lane >> 2);
    float labi[4];
#pragma unroll
    for (int q = 0; q < 4; ++q) labi[q] = s_rlab[rl + q * 8];

    float sAr[4] = {0.f, 0.f, 0.f, 0.f};
    float sWr[4] = {0.f, 0.f, 0.f, 0.f};
    float sDr[4] = {0.f, 0.f, 0.f, 0.f};

#pragma unroll
    for (int nt = 0; nt < 8; ++nt) {
        int clbase = cg * 64 + nt * 8 + ((lane & 3) << 1);
        float lj0 = s_clab[clbase];
        float lj1 = s_clab[clbase + 1];
        float cA[2] = {0.f, 0.f};
        float cW[2] = {0.f, 0.f};
        float cD[2] = {0.f, 0.f};
#pragma unroll
        for (int mt = 0; mt < 2; ++mt) {
#pragma unroll
            for (int e = 0; e < 4; ++e) {
                int q  = mt * 2 + (e >> 1);
                int rr = rl + q * 8;                   // local row
                int cc = clbase + (e & 1);             // local col
                float cosv = acc[mt][nt][e];
                float dy = labi[q] - ((e & 1) ? lj1 : lj0);
                float w  = __expf(dy * dy * -0.5f);
                bool dg  = dtile && (rr == cc);
                float ev = dg ? 0.f : __expf((cosv - 1.0f) * INV_T);
                if (dg) cosv = 1.0f;
                float wc = w * cosv;
                sAr[q] += wc;
                sWr[q] += w;
                sDr[q] += ev;
                int p = e & 1;
                cA[p] += wc;
                cW[p] += w;
                cD[p] += ev;
            }
        }
        // column partials: reduce over this warp's 32 rows (lane>>2 strides)
        if (!dtile) {
#pragma unroll
            for (int p = 0; p < 2; ++p) {
#pragma unroll
                for (int o = 4; o <= 16; o <<= 1) {
                    cA[p] += __shfl_xor_sync(0xffffffffu, cA[p], o);
                    cW[p] += __shfl_xor_sync(0xffffffffu, cW[p], o);
                    cD[p] += __shfl_xor_sync(0xffffffffu, cD[p], o);
                }
            }
            if ((lane >> 2) == 0) {
                int colb = nt * 8 + ((lane & 3) << 1);   // 0..63 within cg
#pragma unroll
                for (int p = 0; p < 2; ++p) {
                    int base = (((cg * 4 + rg) * 64) + colb + p) * 3;
                    scol[base + 0] = cA[p];
                    scol[base + 1] = cW[p];
                    scol[base + 2] = cD[p];
                }
            }
        }
    }

    // Row partials: reduce across the 4 lanes sharing each row
#pragma unroll
    for (int q = 0; q < 4; ++q) {
        sAr[q] += __shfl_xor_sync(0xffffffffu, sAr[q], 1);
        sAr[q] += __shfl_xor_sync(0xffffffffu, sAr[q], 2);
        sWr[q] += __shfl_xor_sync(0xffffffffu, sWr[q], 1);
        sWr[q] += __shfl_xor_sync(0xffffffffu, sWr[q], 2);
        sDr[q] += __shfl_xor_sync(0xffffffffu, sDr[q], 1);
        sDr[q] += __shfl_xor_sync(0xffffffffu, sDr[q], 2);
    }
    if ((lane & 3) == 0) {
        int slot = tJ * 2 + cg;
#pragma unroll
        for (int q = 0; q < 4; ++q) {
            int gi = tI * 128 + rl + q * 8;
            g_pA[(size_t)slot * N_TOT + gi] = sAr[q];
            g_pW[(size_t)slot * N_TOT + gi] = sWr[q];
            g_pD[(size_t)slot * N_TOT + gi] = sDr[q];
        }
    }

    // Column partials: reduce across the 4 rg warps, write to block tJ rows
    if (!dtile) {
        __syncthreads();
        if (tid < 128) {
            int cgx = tid >> 6;
            int col = tid & 63;
            float vA = 0.f, vW = 0.f, vD = 0.f;
#pragma unroll
            for (int r = 0; r < 4; ++r) {
                int base = (((cgx * 4 + r) * 64) + col) * 3;
                vA += scol[base + 0];
                vW += scol[base + 1];
                vD += scol[base + 2];
            }
            int gc = tJ * 128 + cgx * 64 + col;
            int slot = tI * 2 + cgx;
            g_pA[(size_t)slot * N_TOT + gc] = vA;
            g_pW[(size_t)slot * N_TOT + gc] = vW;
            g_pD[(size_t)slot * N_TOT + gc] = vD;
        }
    }
}

// ============================================================================
// Kernel 3: per-row reduction of 128 partial slots -> loss -> block partial
// ============================================================================
__global__ void k_final1() {
    __shared__ float red[32];
    int tid = threadIdx.x;
    int row = blockIdx.x * 256 + tid;   // 32 CTAs x 256 = 8192
    float A = 0.f, W = 0.f, D = 0.f;
#pragma unroll 4
    for (int s = 0; s < 128; ++s) {
        A += g_pA[(size_t)s * N_TOT + row];
        W += g_pW[(size_t)s * N_TOT + row];
        D += g_pD[(size_t)s * N_TOT + row];
    }
    float loss = -((A - W) * INV_T / W - logf(D + 1e-8f));
#pragma unroll
    for (int o = 16; o; o >>= 1) loss += __shfl_xor_sync(0xffffffffu, loss, o);
    if ((tid & 31) == 0) red[tid >> 5] = loss;
    __syncthreads();
    if (tid < 8) {
        float v = red[tid];
#pragma unroll
        for (int o = 4; o; o >>= 1) v += __shfl_xor_sync(0xffu, v, o);
        if (tid == 0) g_bpart[blockIdx.x] = v;
    }
}

// ============================================================================
// Kernel 4: sum 32 block partials -> mean
// ============================================================================
__global__ void k_final2(float* __restrict__ out) {
    int tid = threadIdx.x;  // 32
    float v = g_bpart[tid];
#pragma unroll
    for (int o = 16; o; o >>= 1) v += __shfl_xor_sync(0xffffffffu, v, o);
    if (tid == 0) out[0] = v * (1.0f / (float)N_TOT);
}

// ============================================================================
// Launch
// ============================================================================
extern "C" void kernel_launch(void* const* d_in, const int* in_sizes, int n_in,
                              void* d_out, int out_size) {
    const float* feats  = (const float*)d_in[0];
    const float* labels = (const float*)d_in[1];
    if (n_in >= 2 && in_sizes[0] == BSZ && in_sizes[1] != BSZ) {
        feats  = (const float*)d_in[1];
        labels = (const float*)d_in[0];
    }

    cudaFuncSetAttribute(k_main, cudaFuncAttributeMaxDynamicSharedMemorySize,
                         SMEM_BYTES);

    k_norm<<<N_TOT / 8, 256>>>(feats);
    k_main<<<NPAIR, 256, SMEM_BYTES>>>(labels);
    k_final1<<<32, 256>>>();
    k_final2<<<1, 32>>>((float*)d_out);
}